// round 17
// baseline (speedup 1.0000x reference)
#include <cuda_runtime.h>
#include <cstdint>

#define THREADS 192
#define NCH 12              // 768 / 64 floats per chunk
#define NP1 1369
#define RS 72               // row stride (72 mod 32 = 8 -> conflict-free LDS.64 pairs)
#define ASTG (38*RS)        // 2736 (rows 0-35 data, 36 gw, 37 ones)
#define BSTG (40*RS)        // 2880 (rows 0-35 data, 36 gw, 37 ones, 38-39 zero)

// ---- smem float offsets ----
#define AOF 0               // A stages: 2 * 2736 -> 5472
#define BOF 5472            // B stages: 2 * 2880 -> 11232
#define GWF 11232           // g*w vector 768 -> 12000
#define WPF 12000           // 6 warp sbw partials (+pad) -> 12008
#define STF 12008           // sxx per half-row, 144 -> 12152
#define SXF 12152           // row sums 72 -> 12224
#define SXGF 12224          // row (x.gw) 72 -> 12296
#define RNF 12296           // rsqrt norms 72 -> 12368
#define DUF 12368           // dustbin*10 72 -> 12440
#define UF  12440
#define VF  12477
#define EUF 12514
#define EVF 12551
#define TOTF 12588
#define SGWS 12589
#define SM_FLOATS 12592
#define SM_BYTES (SM_FLOATS*4)   // 50368 -> 4 CTAs/SM
// post-loop aliases (stages dead after main loop)
#define CSF 0               // couplings 1369 (A stage 0)
#define ECF 2736            // exp couplings 1369 (A stage 1)
#define XCF 5472            // kh-merge scratch (B stages)

#define NORMC (-4.27666611901605529f)   // -log(72)
#define LMD   (-0.69314718055994531f)   // log(36)-log(72)

__device__ __forceinline__ void fma2(unsigned long long &d,
                                     unsigned long long a,
                                     unsigned long long b) {
    asm volatile("fma.rn.f32x2 %0, %1, %2, %0;" : "+l"(d) : "l"(a), "l"(b));
}
__device__ __forceinline__ float lo32(unsigned long long a){ return __uint_as_float((unsigned)a); }
__device__ __forceinline__ float hi32(unsigned long long a){ return __uint_as_float((unsigned)(a>>32)); }

__device__ __forceinline__ uint32_t f2tf(float f) {
    uint32_t u; asm("cvt.rna.tf32.f32 %0, %1;" : "=r"(u) : "f"(f)); return u;
}
__device__ __forceinline__ void mma1688(float* d, const uint32_t* a, const uint32_t* b) {
    asm volatile(
        "mma.sync.aligned.m16n8k8.row.col.f32.tf32.tf32.f32 "
        "{%0,%1,%2,%3}, {%4,%5,%6,%7}, {%8,%9}, {%0,%1,%2,%3};"
        : "+f"(d[0]), "+f"(d[1]), "+f"(d[2]), "+f"(d[3])
        : "r"(a[0]), "r"(a[1]), "r"(a[2]), "r"(a[3]), "r"(b[0]), "r"(b[1]));
}
__device__ __forceinline__ void cp16(uint32_t dst, const float* src) {
    asm volatile("cp.async.cg.shared.global [%0], [%1], 16;"
                 :: "r"(dst), "l"(src) : "memory");
}

// one 72-row x 64-float chunk: x rows -> A stage rows 0-35, y rows -> B rows 0-35
__device__ __forceinline__ void load_chunk(uint32_t smb, const float* xb,
                                           const float* yb, int c, int t) {
    uint32_t sA = smb + AOF*4 + (c&1)*(ASTG*4);
    uint32_t sB = smb + BOF*4 + (c&1)*(BSTG*4);
    #pragma unroll
    for (int r = 0; r < 6; ++r) {
        int op = t + THREADS*r;          // 0..1151 exact
        int row = op >> 4, c4 = op & 15;
        if (row < 36)
            cp16(sA + row*(RS*4) + c4*16, xb + row*768 + c*64 + c4*4);
        else
            cp16(sB + (row-36)*(RS*4) + c4*16, yb + (row-36)*768 + c*64 + c4*4);
    }
    asm volatile("cp.async.commit_group;" ::: "memory");
}

// ======================= fused kernel ===================================
__global__ void __launch_bounds__(THREADS, 4)
k_fused(const float* __restrict__ X, const float* __restrict__ Y,
        const float* __restrict__ G, const float* __restrict__ Bln,
        const float* __restrict__ W, const float* __restrict__ Blin,
        float* __restrict__ out, int B)
{
    extern __shared__ __align__(16) float smf[];
    uint32_t smb;
    asm("{ .reg .u64 tt; cvta.to.shared.u64 tt, %1; cvt.u32.u64 %0, tt; }"
        : "=r"(smb) : "l"(smf));
    const int t = threadIdx.x;
    const int w = t >> 5, lid = t & 31;
    const int g = lid >> 2, tig = lid & 3;
    const int b = blockIdx.x;
    const float* xb = X + (size_t)b * 27648;
    const float* yb = Y + (size_t)b * 27648;

    // special rows, both stages: A row 37 = ones; B row 37 = ones, 38/39 = zero
    for (int i = t; i < 2*4*64; i += THREADS) {
        int st = i >> 8; int rem = i & 255;
        int r = rem >> 6, col = rem & 63;
        if (r == 0)      smf[AOF + st*ASTG + 37*RS + col] = 1.f;
        else if (r == 1) smf[BOF + st*BSTG + 37*RS + col] = 1.f;
        else             smf[BOF + st*BSTG + (36+r)*RS + col] = 0.f;
    }

    // prefetch chunks 0,1
    load_chunk(smb, xb, yb, 0, t);
    load_chunk(smb, xb, yb, 1, t);

    // g*w vector + per-warp sbw partial (768 = 4*192 exact)
    {
        float sbw = 0.f;
        float gv0 = 0.f;
        #pragma unroll
        for (int r = 0; r < 4; ++r) {
            int h = t + THREADS*r;
            float wv = W[h];
            float gv = G[h]*wv;
            smf[GWF + h] = gv;
            if (r == 0) gv0 = gv;
            sbw += Bln[h]*wv;
        }
        #pragma unroll
        for (int o = 16; o > 0; o >>= 1)
            sbw += __shfl_down_sync(0xffffffffu, sbw, o);
        if (lid == 0) smf[WPF + w] = sbw;
        if (t < 64) {                       // gw row for chunk 0 (stage 0)
            smf[AOF + 36*RS + t] = gv0;
            smf[BOF + 36*RS + t] = gv0;
        }
        if (t >= 64 && t < 128) {           // gw row for chunk 1 (stage 1)
            float gv = G[t]*W[t];
            smf[AOF + ASTG + 36*RS + (t-64)] = gv;
            smf[BOF + BSTG + 36*RS + (t-64)] = gv;
        }
    }

    // GEMM: warps 0-3: (mg = w>>1, kh = w&1)
    //   mg0: m-tiles rows {0-15, 16-31};  mg1: m-tile rows {22-37}
    //   B fragments loaded once per k-step, reused across m-tiles.
    const int mg = w >> 1;
    const int kh = w & 1;
    float acc0[5][4], acc1[5][4];
    #pragma unroll
    for (int j = 0; j < 5; ++j)
        #pragma unroll
        for (int e = 0; e < 4; ++e) { acc0[j][e] = 0.f; acc1[j][e] = 0.f; }

    // stats (warps 4-5): 64 threads, slices s, s+64, s+128(<144)
    unsigned long long sxx2[3] = {0ULL, 0ULL, 0ULL};
    const int s0 = t - 128;

    #pragma unroll 1
    for (int c = 0; c < NCH; ++c) {
        asm volatile("cp.async.wait_group 0;" ::: "memory");
        __syncthreads();
        if (c + 1 < NCH) {
            load_chunk(smb, xb, yb, c+1, t);
            if (t >= 128) {   // gw row for chunk c+1 (other buffer), stats warps
                int col = t - 128;
                float gv = smf[GWF + (c+1)*64 + col];
                int s2 = (c+1)&1;
                smf[AOF + s2*ASTG + 36*RS + col] = gv;
                smf[BOF + s2*BSTG + 36*RS + col] = gv;
            }
        }

        if (w < 4) {
            const float* Bs  = smf + BOF + (c&1)*BSTG + g*RS + kh*32 + 2*tig;
            const float* As0 = smf + AOF + (c&1)*ASTG
                               + ((mg == 0) ? g : 22 + g)*RS + kh*32 + 2*tig;
            #pragma unroll
            for (int ks = 0; ks < 4; ++ks) {
                const int ko = ks*8;
                uint32_t bf[5][2];
                #pragma unroll
                for (int j = 0; j < 5; ++j) {
                    float2 bb = *reinterpret_cast<const float2*>(
                        Bs + j*8*RS + ko);
                    bf[j][0] = f2tf(bb.x);
                    bf[j][1] = f2tf(bb.y);
                }
                {
                    float2 aLo = *reinterpret_cast<const float2*>(As0 + ko);
                    float2 aHi = *reinterpret_cast<const float2*>(As0 + 8*RS + ko);
                    uint32_t a[4];
                    a[0] = f2tf(aLo.x); a[1] = f2tf(aHi.x);
                    a[2] = f2tf(aLo.y); a[3] = f2tf(aHi.y);
                    #pragma unroll
                    for (int j = 0; j < 5; ++j) mma1688(acc0[j], a, bf[j]);
                }
                if (mg == 0) {   // second m-tile (rows 16-31), reuse bf
                    float2 aLo = *reinterpret_cast<const float2*>(As0 + 16*RS + ko);
                    float2 aHi = *reinterpret_cast<const float2*>(As0 + 24*RS + ko);
                    uint32_t a[4];
                    a[0] = f2tf(aLo.x); a[1] = f2tf(aHi.x);
                    a[2] = f2tf(aLo.y); a[3] = f2tf(aHi.y);
                    #pragma unroll
                    for (int j = 0; j < 5; ++j) mma1688(acc1[j], a, bf[j]);
                }
            }
        } else {
            // ---- per-half-row sxx (warps 4-5, overlaps MMA latency) ----
            #pragma unroll
            for (int sl = 0; sl < 3; ++sl) {
                int sli = s0 + sl*64;
                if (sl < 2 || s0 < 16) {
                    int srow = sli >> 1, shalf = sli & 1;
                    const float* rp = smf + (srow < 36
                        ? AOF + (c&1)*ASTG + srow*RS
                        : BOF + (c&1)*BSTG + (srow-36)*RS) + shalf*32;
                    #pragma unroll
                    for (int j = 0; j < 8; ++j) {
                        ulonglong2 v = *reinterpret_cast<const ulonglong2*>(rp + j*4);
                        fma2(sxx2[sl], v.x, v.x);
                        fma2(sxx2[sl], v.y, v.y);
                    }
                }
            }
        }
    }

    if (w >= 4) {
        #pragma unroll
        for (int sl = 0; sl < 3; ++sl) {
            int sli = s0 + sl*64;
            if (sl < 2 || s0 < 16)
                smf[STF + sli] = lo32(sxx2[sl]) + hi32(sxx2[sl]);
        }
    }

    // ---- merge kh partials via smem scratch (B stages, dead) ----
    if (w == 1) {
        float* sc = smf + XCF + lid*41;
        #pragma unroll
        for (int j = 0; j < 5; ++j)
            #pragma unroll
            for (int e = 0; e < 4; ++e) {
                sc[j*4 + e]      = acc0[j][e];
                sc[20 + j*4 + e] = acc1[j][e];
            }
    }
    if (w == 3) {
        float* sc = smf + XCF + 32*41 + lid*21;
        #pragma unroll
        for (int j = 0; j < 5; ++j)
            #pragma unroll
            for (int e = 0; e < 4; ++e) sc[j*4 + e] = acc0[j][e];
    }
    __syncthreads();
    if (w == 0) {
        const float* sc = smf + XCF + lid*41;
        #pragma unroll
        for (int j = 0; j < 5; ++j)
            #pragma unroll
            for (int e = 0; e < 4; ++e) {
                acc0[j][e] += sc[j*4 + e];
                acc1[j][e] += sc[20 + j*4 + e];
            }
    }
    if (w == 2) {
        const float* sc = smf + XCF + 32*41 + lid*21;
        #pragma unroll
        for (int j = 0; j < 5; ++j)
            #pragma unroll
            for (int e = 0; e < 4; ++e) acc0[j][e] += sc[j*4 + e];
    }

    // ---- extract MMA stats (w0: tiles 0,1; w2: tile rows 22-37) ----
    if (w == 0 || w == 2) {
        const int ntl = (w == 0) ? 2 : 1;
        #pragma unroll
        for (int tt = 0; tt < 2; ++tt) {
            if (tt < ntl) {
                int r0 = (w == 0) ? tt*16 + g : 22 + g;
                float (*ac)[4] = tt ? acc1 : acc0;
                #pragma unroll
                for (int j = 0; j < 5; ++j) {
                    int c0 = j*8 + 2*tig;
                    #pragma unroll
                    for (int e = 0; e < 4; ++e) {
                        int rr = r0 + (e >> 1)*8;
                        int cc = c0 + (e & 1);
                        float val = ac[j][e];
                        if (rr < 36) {
                            if (cc == 36)      smf[SXGF + rr] = val;
                            else if (cc == 37) smf[SXF + rr] = val;
                        } else if (rr == 36) {
                            if (cc < 36)       smf[SXGF + 36 + cc] = val;
                            else if (cc == 37) smf[SGWS] = val;
                        } else if (rr == 37 && cc < 36) {
                            smf[SXF + 36 + cc] = val;
                        }
                    }
                }
            }
        }
    }
    __syncthreads();    // stages fully dead -> aliases live

    // per-row finalize (72 rows)
    if (t < 72) {
        float Sxx = smf[STF + 2*t] + smf[STF + 2*t + 1];
        float Sx  = smf[SXF + t];
        float Sxg = smf[SXGF + t];
        float Sgw = smf[SGWS];
        float Sbw = 0.f;
        #pragma unroll
        for (int j = 0; j < 6; ++j) Sbw += smf[WPF + j];
        smf[RNF + t] = rsqrtf(Sxx);
        float mu  = Sx * (1.f/768.f);
        float var = Sxx * (1.f/768.f) - mu*mu;
        float rsd = rsqrtf(var + 1e-5f);
        smf[DUF + t] = tanhf((Sxg - mu*Sgw)*rsd + Sbw + Blin[0]) * 10.f;
    }
    if (t < 37) {
        smf[UF + t] = 0.f; smf[VF + t] = 0.f;
        smf[EUF + t] = 1.f; smf[EVF + t] = 1.f;
    }
    if (t == 0) smf[TOTF] = 0.f;
    __syncthreads();

    // write scaled couplings (w0: tiles 0,1; w2: tile 22-37; overlap benign)
    if (w == 0 || w == 2) {
        const int ntl = (w == 0) ? 2 : 1;
        #pragma unroll
        for (int tt = 0; tt < 2; ++tt) {
            if (tt < ntl) {
                int r0 = (w == 0) ? tt*16 + g : 22 + g;
                float (*ac)[4] = tt ? acc1 : acc0;
                #pragma unroll
                for (int j = 0; j < 5; ++j) {
                    int c0 = j*8 + 2*tig;
                    #pragma unroll
                    for (int e = 0; e < 4; ++e) {
                        int rr = r0 + (e >> 1)*8;
                        int cc = c0 + (e & 1);
                        if (rr < 36 && cc < 36)
                            smf[CSF + rr*37 + cc] =
                                ac[j][e] * smf[RNF+rr] * smf[RNF+36+cc] * 10.f;
                    }
                }
            }
        }
    }
    if (t < 36) {
        smf[CSF + t*37 + 36] = smf[DUF + t];
        smf[CSF + 36*37 + t] = smf[DUF + 36 + t];
    }
    if (t == 0) smf[CSF + 36*37 + 36] = -1000.f;
    __syncthreads();

    for (int i = t; i < NP1; i += THREADS) smf[ECF + i] = __expf(smf[CSF + i]);
    __syncthreads();

    // ---- Sinkhorn: warps 0-1 only, named barrier ----
    if (t < 64) {
        const int m = t;
        const bool act = t < 37;
        const float lr = (m < 36) ? NORMC : LMD;
        #pragma unroll 1
        for (int it = 0; it < 20; ++it) {
            if (act) {
                const float* er = smf + ECF + m*37;
                float s0f=0.f, s1=0.f, s2=0.f, s3=0.f;
                #pragma unroll
                for (int n = 0; n < 36; n += 4) {
                    s0f = fmaf(er[n+0], smf[EVF+n+0], s0f);
                    s1  = fmaf(er[n+1], smf[EVF+n+1], s1);
                    s2  = fmaf(er[n+2], smf[EVF+n+2], s2);
                    s3  = fmaf(er[n+3], smf[EVF+n+3], s3);
                }
                s0f = fmaf(er[36], smf[EVF+36], s0f);
                float uu = lr - __logf((s0f+s1)+(s2+s3));
                smf[UF + m] = uu;
                smf[EUF + m] = __expf(uu);
            }
            asm volatile("bar.sync 5, 64;" ::: "memory");
            if (act) {
                const float* ecc = smf + ECF + m;
                float s0f=0.f, s1=0.f, s2=0.f, s3=0.f;
                #pragma unroll
                for (int n = 0; n < 36; n += 4) {
                    s0f = fmaf(ecc[(n+0)*37], smf[EUF+n+0], s0f);
                    s1  = fmaf(ecc[(n+1)*37], smf[EUF+n+1], s1);
                    s2  = fmaf(ecc[(n+2)*37], smf[EUF+n+2], s2);
                    s3  = fmaf(ecc[(n+3)*37], smf[EUF+n+3], s3);
                }
                s0f = fmaf(ecc[36*37], smf[EUF+36], s0f);
                float vv = lr - __logf((s0f+s1)+(s2+s3));
                smf[VF + m] = vv;
                smf[EVF + m] = __expf(vv);
            }
            asm volatile("bar.sync 5, 64;" ::: "memory");
        }
    }
    __syncthreads();

    // ---- epilogue: Z + total;  exp(Z) = 72 * ec * eu * ev ----
    float* ob = out + (size_t)b * NP1;
    float part = 0.f;
    for (int i = t; i < NP1; i += THREADS) {
        int mm = i / 37;
        int nn = i - mm*37;
        float cc = smf[CSF + i];
        ob[i] = cc + smf[UF + mm] + smf[VF + nn] - NORMC;
        if (mm < 36 && nn < 36)
            part += smf[ECF + i] * smf[EUF + mm] * smf[EVF + nn] * cc;
    }
    #pragma unroll
    for (int o = 16; o > 0; o >>= 1)
        part += __shfl_down_sync(0xffffffffu, part, o);
    if (lid == 0) atomicAdd(&smf[TOTF], part * 72.f);
    __syncthreads();
    if (t == 0) out[(size_t)B*NP1 + b] = smf[TOTF];
}

// ======================= launch =========================================
extern "C" void kernel_launch(void* const* d_in, const int* in_sizes, int n_in,
                              void* d_out, int out_size)
{
    const float* x  = (const float*)d_in[0];
    const float* y  = (const float*)d_in[1];
    const float* g  = (const float*)d_in[2];
    const float* bb = (const float*)d_in[3];
    const float* w  = (const float*)d_in[4];
    const float* bl = (const float*)d_in[5];
    const int B = in_sizes[0] / (36 * 768);
    float* out = (float*)d_out;

    cudaFuncSetAttribute(k_fused,
                         cudaFuncAttributeMaxDynamicSharedMemorySize, SM_BYTES);
    k_fused<<<B, THREADS, SM_BYTES>>>(x, y, g, bb, w, bl, out, B);
}